// round 1
// baseline (speedup 1.0000x reference)
#include <cuda_runtime.h>
#include <cstdint>

#define BB 4096
#define TT 512
#define IND 5
#define E 30
#define NH 3
#define HD 10
#define KSPLIT 8
#define KTILE 512   // 4096 / KSPLIT
#define QTILE 128

// ---------------- scratch (device globals; no allocations allowed) ----------
__device__ float g_hn[BB * E];
__device__ float g_cn[BB * E];
__device__ float g_q[BB * E];
__device__ float g_k[BB * E];
__device__ float g_v[BB * E];
__device__ float g_psum[NH * KSPLIT * BB];
__device__ float g_pacc[NH * KSPLIT * BB * HD];

// ---------------- helpers ----------------------------------------------------
__device__ __forceinline__ float fsigmoid(float x) {
    return __fdividef(1.0f, 1.0f + __expf(-x));
}
__device__ __forceinline__ float ftanh(float x) {
    // tanh(x) = 2*sigmoid(2x) - 1
    return __fdividef(2.0f, 1.0f + __expf(-2.0f * x)) - 1.0f;
}

// FMA-pipe exp (no MUFU): exp(x) = 2^(x*log2e), poly for 2^f on [-0.5,0.5]
__device__ __forceinline__ float fexp(float x) {
    x = fmaxf(fminf(x, 60.0f), -60.0f);
    float t = x * 1.442695040888963f;
    float r = t + 12582912.0f;                  // round-to-nearest via magic
    int   i = __float_as_int(r) - 0x4B400000;   // integer part
    float f = t - (r - 12582912.0f);            // frac in [-0.5, 0.5]
    float p = 1.33335581e-3f;
    p = fmaf(p, f, 9.61812911e-3f);
    p = fmaf(p, f, 5.55041087e-2f);
    p = fmaf(p, f, 2.40226507e-1f);
    p = fmaf(p, f, 6.93147180e-1f);
    p = fmaf(p, f, 1.0f);
    return __int_as_float(__float_as_int(p) + (int)((unsigned)i << 23));
}

__device__ __forceinline__ float warp_sum(float v) {
    #pragma unroll
    for (int o = 16; o > 0; o >>= 1) v += __shfl_xor_sync(0xffffffffu, v, o);
    return v;
}

// ---------------- kernel 1: LSTM (one warp per batch row, all 512 steps) -----
__global__ __launch_bounds__(256, 1) void lstm_kernel(
    const float* __restrict__ input, const float* __restrict__ w_ih,
    const float* __restrict__ w_hh, const float* __restrict__ b_ih,
    const float* __restrict__ b_hh)
{
    int warp = (blockIdx.x * blockDim.x + threadIdx.x) >> 5;
    int lane = threadIdx.x & 31;
    bool act = lane < E;
    int li = act ? lane : 0;

    // per-lane weights in registers: rows li, E+li, 2E+li, 3E+li (gates i,f,g,o)
    float wih0[IND], wih1[IND], wih2[IND], wih3[IND];
    #pragma unroll
    for (int k = 0; k < IND; k++) {
        wih0[k] = __ldg(w_ih + (0 * E + li) * IND + k);
        wih1[k] = __ldg(w_ih + (1 * E + li) * IND + k);
        wih2[k] = __ldg(w_ih + (2 * E + li) * IND + k);
        wih3[k] = __ldg(w_ih + (3 * E + li) * IND + k);
    }
    float whh0[E], whh1[E], whh2[E], whh3[E];
    #pragma unroll
    for (int j = 0; j < E; j++) {
        whh0[j] = __ldg(w_hh + (0 * E + li) * E + j);
        whh1[j] = __ldg(w_hh + (1 * E + li) * E + j);
        whh2[j] = __ldg(w_hh + (2 * E + li) * E + j);
        whh3[j] = __ldg(w_hh + (3 * E + li) * E + j);
    }
    float bi = __ldg(b_ih + 0 * E + li) + __ldg(b_hh + 0 * E + li);
    float bf = __ldg(b_ih + 1 * E + li) + __ldg(b_hh + 1 * E + li);
    float bg = __ldg(b_ih + 2 * E + li) + __ldg(b_hh + 2 * E + li);
    float bo = __ldg(b_ih + 3 * E + li) + __ldg(b_hh + 3 * E + li);

    const float* xp = input + (size_t)warp * TT * IND;
    float h = 0.0f, c = 0.0f;

    float xv[IND];
    #pragma unroll
    for (int k = 0; k < IND; k++) xv[k] = __ldg(xp + k);

    for (int t = 0; t < TT; t++) {
        // prefetch next step's x while computing this step
        float xn[IND];
        const float* xnp = xp + IND;
        if (t + 1 < TT) {
            #pragma unroll
            for (int k = 0; k < IND; k++) xn[k] = __ldg(xnp + k);
        } else {
            #pragma unroll
            for (int k = 0; k < IND; k++) xn[k] = 0.0f;
        }
        xp = xnp;

        float ai = bi, af = bf, ag = bg, ao = bo;
        #pragma unroll
        for (int k = 0; k < IND; k++) {
            ai = fmaf(wih0[k], xv[k], ai);
            af = fmaf(wih1[k], xv[k], af);
            ag = fmaf(wih2[k], xv[k], ag);
            ao = fmaf(wih3[k], xv[k], ao);
        }
        #pragma unroll
        for (int j = 0; j < E; j++) {
            float hj = __shfl_sync(0xffffffffu, h, j);
            ai = fmaf(whh0[j], hj, ai);
            af = fmaf(whh1[j], hj, af);
            ag = fmaf(whh2[j], hj, ag);
            ao = fmaf(whh3[j], hj, ao);
        }
        float ig = fsigmoid(ai);
        float fg = fsigmoid(af);
        float gg = ftanh(ag);
        float og = fsigmoid(ao);
        c = fmaf(fg, c, ig * gg);
        h = og * ftanh(c);

        #pragma unroll
        for (int k = 0; k < IND; k++) xv[k] = xn[k];
    }
    if (act) {
        g_hn[(size_t)warp * E + lane] = h;
        g_cn[(size_t)warp * E + lane] = c;
    }
}

// ---------------- kernel 2: QKV projections (warp per row) --------------------
__global__ __launch_bounds__(256) void qkv_kernel(
    const float* __restrict__ ipw, const float* __restrict__ ipb)
{
    int warp = (blockIdx.x * blockDim.x + threadIdx.x) >> 5;
    int lane = threadIdx.x & 31;
    bool act = lane < E;
    int li = act ? lane : 0;

    float h = g_hn[(size_t)warp * E + li];
    float c = g_cn[(size_t)warp * E + li];
    float aq = __ldg(ipb + 0 * E + li);
    float ak = __ldg(ipb + 1 * E + li);
    float av = __ldg(ipb + 2 * E + li);
    #pragma unroll
    for (int j = 0; j < E; j++) {
        float hj = __shfl_sync(0xffffffffu, h, j);
        float cj = __shfl_sync(0xffffffffu, c, j);
        aq = fmaf(__ldg(ipw + (0 * E + li) * E + j), hj, aq);
        ak = fmaf(__ldg(ipw + (1 * E + li) * E + j), cj, ak);
        av = fmaf(__ldg(ipw + (2 * E + li) * E + j), cj, av);
    }
    if (act) {
        g_q[(size_t)warp * E + lane] = aq;
        g_k[(size_t)warp * E + lane] = ak;
        g_v[(size_t)warp * E + lane] = av;
    }
}

// ---------------- kernel 3: attention partials (no-max softmax, poly exp) -----
__global__ __launch_bounds__(128) void attn_kernel()
{
    __shared__ float ks[KTILE * HD];
    __shared__ float vs[KTILE * HD];
    int h   = blockIdx.z;
    int qc  = blockIdx.x;
    int ksp = blockIdx.y;
    int tid = threadIdx.x;
    int qi  = qc * QTILE + tid;
    int k0  = ksp * KTILE;

    for (int i = tid; i < KTILE * HD; i += 128) {
        int m = i / HD, d = i - m * HD;
        ks[i] = g_k[(size_t)(k0 + m) * E + h * HD + d];
        vs[i] = g_v[(size_t)(k0 + m) * E + h * HD + d];
    }
    __syncthreads();

    float qr[HD];
    #pragma unroll
    for (int d = 0; d < HD; d++)
        qr[d] = g_q[(size_t)qi * E + h * HD + d] * 0.3162277660168379f; // 1/sqrt(10)

    float acc[HD];
    #pragma unroll
    for (int d = 0; d < HD; d++) acc[d] = 0.0f;
    float s = 0.0f;

    #pragma unroll 2
    for (int m = 0; m < KTILE; m++) {
        float sc = 0.0f;
        #pragma unroll
        for (int d = 0; d < HD; d++) sc = fmaf(qr[d], ks[m * HD + d], sc);
        float p = fexp(sc);
        s += p;
        #pragma unroll
        for (int d = 0; d < HD; d++) acc[d] = fmaf(p, vs[m * HD + d], acc[d]);
    }

    int base = (h * KSPLIT + ksp) * BB + qi;
    g_psum[base] = s;
    #pragma unroll
    for (int d = 0; d < HD; d++) g_pacc[(size_t)base * HD + d] = acc[d];
}

// ---------------- kernel 4: combine + out_proj + LN + MLP + LN + head --------
__global__ __launch_bounds__(256) void epi_kernel(
    const float* __restrict__ opw, const float* __restrict__ opb,
    const float* __restrict__ f1w, const float* __restrict__ f1b,
    const float* __restrict__ f2w, const float* __restrict__ f2b,
    const float* __restrict__ lng, const float* __restrict__ lnb,
    const float* __restrict__ ow,  const float* __restrict__ ob,
    float* __restrict__ out)
{
    int warp = (blockIdx.x * blockDim.x + threadIdx.x) >> 5;
    int lane = threadIdx.x & 31;
    bool act = lane < E;
    int li = act ? lane : 0;
    int hh = li / HD, dd = li - hh * HD;

    // combine split-softmax partials
    float num = 0.0f, den = 0.0f;
    #pragma unroll
    for (int ksp = 0; ksp < KSPLIT; ksp++) {
        int base = (hh * KSPLIT + ksp) * BB + warp;
        num += g_pacc[(size_t)base * HD + dd];
        den += g_psum[base];
    }
    float ctx = __fdividef(num, den);

    // out_proj
    float ao = __ldg(opb + li);
    #pragma unroll
    for (int j = 0; j < E; j++) {
        float cj = __shfl_sync(0xffffffffu, ctx, j);
        ao = fmaf(__ldg(opw + li * E + j), cj, ao);
    }
    float r1 = ao + g_hn[(size_t)warp * E + li];

    // LN1
    float lg = __ldg(lng + li), lb = __ldg(lnb + li);
    float mu = warp_sum(act ? r1 : 0.0f) * (1.0f / E);
    float dv = act ? (r1 - mu) : 0.0f;
    float var = warp_sum(dv * dv) * (1.0f / E);
    float x1 = fmaf(dv * rsqrtf(var + 1e-5f), lg, lb);
    if (!act) x1 = 0.0f;

    // fc1 + exact GELU
    float y = __ldg(f1b + li);
    #pragma unroll
    for (int j = 0; j < E; j++) {
        float xj = __shfl_sync(0xffffffffu, x1, j);
        y = fmaf(__ldg(f1w + li * E + j), xj, y);
    }
    float gy = 0.5f * y * (1.0f + erff(y * 0.7071067811865475f));

    // fc2
    float z = __ldg(f2b + li);
    #pragma unroll
    for (int j = 0; j < E; j++) {
        float gj = __shfl_sync(0xffffffffu, gy, j);
        z = fmaf(__ldg(f2w + li * E + j), gj, z);
    }
    float r2 = x1 + z;

    // LN2
    float mu2 = warp_sum(act ? r2 : 0.0f) * (1.0f / E);
    float dv2 = act ? (r2 - mu2) : 0.0f;
    float var2 = warp_sum(dv2 * dv2) * (1.0f / E);
    float x2 = fmaf(dv2 * rsqrtf(var2 + 1e-5f), lg, lb);
    if (!act) x2 = 0.0f;

    // final head [E -> 3]
    float o0 = __ldg(ob + 0), o1 = __ldg(ob + 1), o2 = __ldg(ob + 2);
    #pragma unroll
    for (int j = 0; j < E; j++) {
        float xj = __shfl_sync(0xffffffffu, x2, j);
        o0 = fmaf(__ldg(ow + 0 * E + j), xj, o0);
        o1 = fmaf(__ldg(ow + 1 * E + j), xj, o1);
        o2 = fmaf(__ldg(ow + 2 * E + j), xj, o2);
    }
    if (lane == 0) {
        out[(size_t)warp * 3 + 0] = o0;
        out[(size_t)warp * 3 + 1] = o1;
        out[(size_t)warp * 3 + 2] = o2;
    }
}

// ---------------- launch ------------------------------------------------------
extern "C" void kernel_launch(void* const* d_in, const int* in_sizes, int n_in,
                              void* d_out, int out_size)
{
    const float* input = (const float*)d_in[0];   // [4096,512,5]
    const float* w_ih  = (const float*)d_in[1];   // [120,5]
    const float* w_hh  = (const float*)d_in[2];   // [120,30]
    const float* b_ih  = (const float*)d_in[3];   // [120]
    const float* b_hh  = (const float*)d_in[4];   // [120]
    const float* ipw   = (const float*)d_in[5];   // [90,30]
    const float* ipb   = (const float*)d_in[6];   // [90]
    const float* opw   = (const float*)d_in[7];   // [30,30]
    const float* opb   = (const float*)d_in[8];   // [30]
    const float* f1w   = (const float*)d_in[9];   // [30,30]
    const float* f1b   = (const float*)d_in[10];  // [30]
    const float* f2w   = (const float*)d_in[11];  // [30,30]
    const float* f2b   = (const float*)d_in[12];  // [30]
    const float* lng   = (const float*)d_in[13];  // [30]
    const float* lnb   = (const float*)d_in[14];  // [30]
    const float* ow    = (const float*)d_in[15];  // [3,30]
    const float* ob    = (const float*)d_in[16];  // [3]
    float* out = (float*)d_out;

    lstm_kernel<<<BB / 8, 256>>>(input, w_ih, w_hh, b_ih, b_hh);
    qkv_kernel<<<BB / 8, 256>>>(ipw, ipb);
    attn_kernel<<<dim3(BB / QTILE, KSPLIT, NH), 128>>>();
    epi_kernel<<<BB / 8, 256>>>(opw, opb, f1w, f1b, f2w, f2b, lng, lnb, ow, ob, out);
}